// round 9
// baseline (speedup 1.0000x reference)
#include <cuda_runtime.h>
#include <cuda_fp16.h>
#include <math_constants.h>
#include <cstdint>

// ---------------------------------------------------------------------------
// HigherOrderAttention — R9: KSPLIT 6 -> 12 (576 attn blocks, 3 blocks/SM)
//   Everything else identical to R8 (validated).
// ---------------------------------------------------------------------------

#define TOK_B   2
#define SEQ     192
#define DIMM    512
#define HEADS   8
#define DH      64
#define BHD     (TOK_B * HEADS)        // 16
#define QKV_C   2560
#define ROWS    (TOK_B * SEQ)          // 384
#define KSPLIT  12
#define KRANGE  (SEQ / KSPLIT)         // 16
#define ITILE   64
#define NWARP   4
#define NTHR    (NWARP * 32)           // 128
#define NJC     (SEQ / 32)             // 6

#define M_LOG2  7.2134752f             // 5 * log2(e)
#define QSCALE  0.18033688f            // 0.125 * log2(e)

// Scratch (device globals)
__device__ float  g_qkv [ROWS * QKV_C];
__device__ __half g_hq  [BHD * SEQ * DH];
__device__ __half g_hk1 [BHD * SEQ * DH];
__device__ __half g_hk2 [BHD * SEQ * DH];
__device__ __half g_hv1 [BHD * SEQ * DH];
__device__ __half g_hv2 [BHD * SEQ * DH];
__device__ float  g_pacc[KSPLIT * BHD * SEQ * DH];
__device__ float  g_pl  [KSPLIT * BHD * SEQ];
__device__ __half g_th  [ROWS * DIMM],  g_tl  [ROWS * DIMM];
__device__ __half g_wqh [QKV_C * DIMM], g_wql [QKV_C * DIMM];
__device__ __half g_woh [DIMM * DIMM],  g_wol [DIMM * DIMM];
__device__ __half g_ah  [ROWS * DIMM],  g_al  [ROWS * DIMM];

// ---------------------------------------------------------------------------
__device__ __forceinline__ void mma16816(float c[4],
                                         unsigned a0, unsigned a1,
                                         unsigned a2, unsigned a3,
                                         unsigned b0, unsigned b1)
{
    asm volatile(
        "mma.sync.aligned.m16n8k16.row.col.f32.f16.f16.f32 "
        "{%0,%1,%2,%3},{%4,%5,%6,%7},{%8,%9},{%0,%1,%2,%3};\n"
        : "+f"(c[0]), "+f"(c[1]), "+f"(c[2]), "+f"(c[3])
        : "r"(a0), "r"(a1), "r"(a2), "r"(a3), "r"(b0), "r"(b1));
}

__device__ __forceinline__ void ldsm_x4(unsigned r[4], const __half* p)
{
    unsigned sa = (unsigned)__cvta_generic_to_shared(p);
    asm volatile("ldmatrix.sync.aligned.m8n8.x4.shared.b16 {%0,%1,%2,%3}, [%4];"
                 : "=r"(r[0]), "=r"(r[1]), "=r"(r[2]), "=r"(r[3]) : "r"(sa));
}

__device__ __forceinline__ unsigned hmul2u(unsigned a, __half2 b)
{
    __half2 av = *reinterpret_cast<__half2*>(&a);
    __half2 r  = __hmul2(av, b);
    return *reinterpret_cast<unsigned*>(&r);
}

__device__ __forceinline__ __half2 u2h2(unsigned a)
{
    return *reinterpret_cast<__half2*>(&a);
}

__device__ __forceinline__ unsigned p2exp(float a, float b)
{
    __half2 h = __floats2half2_rn(a, b);
    unsigned x = *reinterpret_cast<unsigned*>(&h);
    unsigned r;
    asm("ex2.approx.f16x2 %0, %1;" : "=r"(r) : "r"(x));
    return r;
}

// ---------------------------------------------------------------------------
// Fused fp32 -> (hi,lo) fp16 split for 3 arrays. i indexes float4 quads.
// ---------------------------------------------------------------------------
__device__ __forceinline__ void split_quad(const float* __restrict__ x,
                                           __half* __restrict__ hi,
                                           __half* __restrict__ lo, int i)
{
    float4 v = ((const float4*)x)[i];
    __half hx = __float2half_rn(v.x), hy = __float2half_rn(v.y);
    __half hz = __float2half_rn(v.z), hw = __float2half_rn(v.w);
    ((__half2*)hi)[2 * i]     = __halves2half2(hx, hy);
    ((__half2*)hi)[2 * i + 1] = __halves2half2(hz, hw);
    ((__half2*)lo)[2 * i]     = __halves2half2(
        __float2half_rn(v.x - __half2float(hx)),
        __float2half_rn(v.y - __half2float(hy)));
    ((__half2*)lo)[2 * i + 1] = __halves2half2(
        __float2half_rn(v.z - __half2float(hz)),
        __float2half_rn(v.w - __half2float(hw)));
}

#define N0Q (ROWS * DIMM / 4)
#define N1Q (QKV_C * DIMM / 4)
#define N2Q (DIMM * DIMM / 4)

__global__ __launch_bounds__(256) void split3_fp16(
    const float* __restrict__ x0, __half* __restrict__ h0, __half* __restrict__ l0,
    const float* __restrict__ x1, __half* __restrict__ h1, __half* __restrict__ l1,
    const float* __restrict__ x2, __half* __restrict__ h2, __half* __restrict__ l2)
{
    int i = blockIdx.x * 256 + threadIdx.x;
    if (i < N0Q) {
        split_quad(x0, h0, l0, i);
    } else if (i < N0Q + N1Q) {
        split_quad(x1, h1, l1, i - N0Q);
    } else if (i < N0Q + N1Q + N2Q) {
        split_quad(x2, h2, l2, i - N0Q - N1Q);
    }
}

// ---------------------------------------------------------------------------
// Tensor-core NT GEMM on pre-split hi/lo fp16, ldmatrix + double buffer.
// ---------------------------------------------------------------------------
#define GS 40   // smem row stride in halves (80B, 16B-aligned for ldmatrix)

__global__ __launch_bounds__(256) void gemm_nt_tch(
    const __half* __restrict__ Ah_, const __half* __restrict__ Al_,
    const __half* __restrict__ Bh_, const __half* __restrict__ Bl_,
    float* __restrict__ C, int M, int N, int K)
{
    __shared__ __half sm[2][4][64 * GS];   // [buf][Ah,Al,Bh,Bl]

    const int t    = threadIdx.x;
    const int m0   = blockIdx.y * 64;
    const int n0   = blockIdx.x * 64;
    const int warp = t >> 5;
    const int lane = t & 31;
    const int g    = lane >> 2;
    const int tg   = lane & 3;
    const int wm   = warp >> 1;   // 0..3
    const int wn   = warp & 1;    // 0..1

    const int lrow = t >> 2;          // 0..63
    const int lc8  = (t & 3) * 8;     // 0,8,16,24

    const int a_off = (wm * 16 + (lane & 15)) * GS + 8 * (lane >> 4);
    const int b_row = wn * 32 + (lane & 7) + ((lane >> 4) & 1) * 8;
    const int b_c8  = ((lane >> 3) & 1) * 8;

    float c[4][4];
#pragma unroll
    for (int a = 0; a < 4; ++a)
#pragma unroll
        for (int b = 0; b < 4; ++b) c[a][b] = 0.f;

    const int NIT = K >> 5;
    uint4 ra, rb, rc, rd;

    {
        size_t ga = (size_t)(m0 + lrow) * K + lc8;
        size_t gb = (size_t)(n0 + lrow) * K + lc8;
        ra = *(const uint4*)(Ah_ + ga);
        rb = *(const uint4*)(Al_ + ga);
        rc = *(const uint4*)(Bh_ + gb);
        rd = *(const uint4*)(Bl_ + gb);
        __half* p = &sm[0][0][lrow * GS + lc8];
        *(uint4*)(p)               = ra;
        *(uint4*)(p + 64 * GS)     = rb;
        *(uint4*)(p + 2 * 64 * GS) = rc;
        *(uint4*)(p + 3 * 64 * GS) = rd;
    }
    __syncthreads();

#pragma unroll 1
    for (int it = 0; it < NIT; ++it) {
        const int cur = it & 1;

        if (it + 1 < NIT) {
            size_t ga = (size_t)(m0 + lrow) * K + (it + 1) * 32 + lc8;
            size_t gb = (size_t)(n0 + lrow) * K + (it + 1) * 32 + lc8;
            ra = *(const uint4*)(Ah_ + ga);
            rb = *(const uint4*)(Al_ + ga);
            rc = *(const uint4*)(Bh_ + gb);
            rd = *(const uint4*)(Bl_ + gb);
        }

        const __half* Ahs = sm[cur][0];
        const __half* Als = sm[cur][1];
        const __half* Bhs = sm[cur][2];
        const __half* Bls = sm[cur][3];

#pragma unroll
        for (int kc = 0; kc < 2; ++kc) {
            const int ko = kc * 16;
            unsigned ah[4], al[4];
            ldsm_x4(ah, Ahs + a_off + ko);
            ldsm_x4(al, Als + a_off + ko);
#pragma unroll
            for (int p = 0; p < 2; ++p) {
                unsigned bh[4], bl[4];
                const int bo = (b_row + p * 16) * GS + ko + b_c8;
                ldsm_x4(bh, Bhs + bo);
                ldsm_x4(bl, Bls + bo);
                mma16816(c[2 * p],     ah[0], ah[1], ah[2], ah[3], bh[0], bh[1]);
                mma16816(c[2 * p],     ah[0], ah[1], ah[2], ah[3], bl[0], bl[1]);
                mma16816(c[2 * p],     al[0], al[1], al[2], al[3], bh[0], bh[1]);
                mma16816(c[2 * p + 1], ah[0], ah[1], ah[2], ah[3], bh[2], bh[3]);
                mma16816(c[2 * p + 1], ah[0], ah[1], ah[2], ah[3], bl[2], bl[3]);
                mma16816(c[2 * p + 1], al[0], al[1], al[2], al[3], bh[2], bh[3]);
            }
        }

        if (it + 1 < NIT) {
            __half* p = &sm[cur ^ 1][0][lrow * GS + lc8];
            *(uint4*)(p)               = ra;
            *(uint4*)(p + 64 * GS)     = rb;
            *(uint4*)(p + 2 * 64 * GS) = rc;
            *(uint4*)(p + 3 * 64 * GS) = rd;
            __syncthreads();
        }
    }

    const int row0 = m0 + wm * 16 + g;
    const int row1 = row0 + 8;
#pragma unroll
    for (int nt = 0; nt < 4; ++nt) {
        const int col = n0 + wn * 32 + nt * 8 + 2 * tg;
        *(float2*)(C + (size_t)row0 * N + col) = make_float2(c[nt][0], c[nt][1]);
        *(float2*)(C + (size_t)row1 * N + col) = make_float2(c[nt][2], c[nt][3]);
    }
}

// ---------------------------------------------------------------------------
// RMSNorm + head split; emits fp16 (q pre-scaled by 0.125*log2e).
// ---------------------------------------------------------------------------
__device__ __forceinline__ void rms_one_h(const float* __restrict__ x,
                                          const float* __restrict__ w,
                                          __half* __restrict__ y, int lane,
                                          float scale)
{
    float x0 = x[lane];
    float x1 = x[lane + 32];
    float ss = x0 * x0 + x1 * x1;
#pragma unroll
    for (int o = 16; o >= 1; o >>= 1)
        ss += __shfl_xor_sync(0xffffffffu, ss, o);
    float inv = rsqrtf(ss * (1.0f / 64.0f) + 1.1920929e-07f) * scale;
    y[lane]      = __float2half(x0 * inv * w[lane]);
    y[lane + 32] = __float2half(x1 * inv * w[lane + 32]);
}

__global__ __launch_bounds__(256) void rmsnorm_kernel(
    const float* __restrict__ qkv,
    const float* __restrict__ qw,  const float* __restrict__ k1w,
    const float* __restrict__ k2w, const float* __restrict__ v1w,
    const float* __restrict__ v2w,
    __half* __restrict__ hq,  __half* __restrict__ hk1, __half* __restrict__ hk2,
    __half* __restrict__ hv1, __half* __restrict__ hv2)
{
    const int wid  = threadIdx.x >> 5;
    const int lane = threadIdx.x & 31;
    const int id   = blockIdx.x * 8 + wid;
    const int h    = id & 7;
    const int bn   = id >> 3;
    const int b    = bn / SEQ;
    const int n    = bn % SEQ;

    const float* base = qkv + bn * QKV_C;
    const int dst = ((b * HEADS + h) * SEQ + n) * DH;

    rms_one_h(base + h * DH,              qw,  hq  + dst, lane, QSCALE);
    rms_one_h(base + 512  + h * 128,      k1w, hk1 + dst, lane, 1.0f);
    rms_one_h(base + 512  + h * 128 + DH, k2w, hk2 + dst, lane, 1.0f);
    rms_one_h(base + 1536 + h * 128,      v1w, hv1 + dst, lane, 1.0f);
    rms_one_h(base + 1536 + h * 128 + DH, v2w, hv2 + dst, lane, 1.0f);
}

// ---------------------------------------------------------------------------
// Tensor-core attention, static-max softmax (identical math to R8).
// ---------------------------------------------------------------------------
#define K1_STRIDE 72
#define SM_K1   (SEQ * K1_STRIDE)
#define SM_V1T  (DH * 200)
#define SM_Q    (ITILE * DH)
#define SM_K2   (KRANGE * DH)
#define SM_V2   (KRANGE * DH)
#define ATTN_SMEM_HALVES (SM_K1 + SM_V1T + SM_Q + SM_K2 + SM_V2)
#define ATTN_SMEM_BYTES  (ATTN_SMEM_HALVES * 2)

__global__ __launch_bounds__(NTHR, 3) void attn_mma(
    const __half* __restrict__ hq,  const __half* __restrict__ hk1,
    const __half* __restrict__ hk2, const __half* __restrict__ hv1,
    const __half* __restrict__ hv2,
    float* __restrict__ pacc, float* __restrict__ pl)
{
    extern __shared__ __align__(16) __half smh[];
    __half*  k1s  = smh;
    __half*  v1t  = k1s + SM_K1;
    __half*  qs   = v1t + SM_V1T;
    __half2* k2t2 = (__half2*)(qs + SM_Q);
    __half*  v2t  = qs + SM_Q + SM_K2;

    const int split = blockIdx.x;
    const int i0    = blockIdx.y * ITILE;
    const int bh    = blockIdx.z;
    const int t     = threadIdx.x;
    const int kbeg  = split * KRANGE;

    const __half* k1b = hk1 + bh * SEQ * DH;
    const __half* v1b = hv1 + bh * SEQ * DH;
    const __half* k2b = hk2 + (bh * SEQ + kbeg) * DH;
    const __half* v2b = hv2 + (bh * SEQ + kbeg) * DH;
    const __half* qb  = hq  + (bh * SEQ + i0) * DH;

    for (int e = t; e < SEQ * DH; e += NTHR) {
        int j = e >> 6, d = e & 63;
        k1s[j * K1_STRIDE + d] = k1b[e];
        v1t[d * 200 + j]       = v1b[e];
    }
    for (int e = t; e < ITILE * DH; e += NTHR) qs[e] = qb[e];
    for (int e = t; e < KRANGE * 32; e += NTHR) {
        int kk = e >> 5, r = e & 31;
        int tg_ = r >> 3, s = r & 7;
        int col = (s >> 1) * 16 + (s & 1) * 8 + tg_ * 2;
        k2t2[e] = *(const __half2*)(k2b + kk * DH + col);
    }
    for (int e = t; e < KRANGE * 64; e += NTHR) {
        int kk = e >> 6, r = e & 63;
        int g_ = r >> 3, nt = r & 7;
        v2t[e] = v2b[kk * DH + nt * 8 + g_];
    }
    __syncthreads();

    const int warp = t >> 5;
    const int lane = t & 31;
    const int g    = lane >> 2;
    const int tg   = lane & 3;

    const unsigned BONES = 0x3C003C00u;

    unsigned qa[4][4];
    {
        const __half* qr0 = qs + (warp * 16 + g) * DH;
        const __half* qr8 = qs + (warp * 16 + g + 8) * DH;
#pragma unroll
        for (int kc = 0; kc < 4; ++kc) {
            qa[kc][0] = *(const unsigned*)(qr0 + kc * 16 + 2 * tg);
            qa[kc][1] = *(const unsigned*)(qr8 + kc * 16 + 2 * tg);
            qa[kc][2] = *(const unsigned*)(qr0 + kc * 16 + 2 * tg + 8);
            qa[kc][3] = *(const unsigned*)(qr8 + kc * 16 + 2 * tg + 8);
        }
    }

    float pv[8][4];
#pragma unroll
    for (int n = 0; n < 8; ++n)
#pragma unroll
        for (int r = 0; r < 4; ++r) pv[n][r] = 0.f;
    float cl[4] = {0.f, 0.f, 0.f, 0.f};

#pragma unroll 1
    for (int jc = 0; jc < NJC; ++jc) {
        unsigned bsf[4][4][2];
        unsigned bvf[2][8][2];
#pragma unroll
        for (int nt = 0; nt < 4; ++nt) {
            const __half* kr = k1s + (jc * 32 + nt * 8 + g) * K1_STRIDE + 2 * tg;
#pragma unroll
            for (int kc = 0; kc < 4; ++kc) {
                bsf[kc][nt][0] = *(const unsigned*)(kr + kc * 16);
                bsf[kc][nt][1] = *(const unsigned*)(kr + kc * 16 + 8);
            }
        }
#pragma unroll
        for (int nt = 0; nt < 8; ++nt) {
            const __half* vr = v1t + (nt * 8 + g) * 200 + jc * 32 + 2 * tg;
#pragma unroll
            for (int kc = 0; kc < 2; ++kc) {
                bvf[kc][nt][0] = *(const unsigned*)(vr + kc * 16);
                bvf[kc][nt][1] = *(const unsigned*)(vr + kc * 16 + 8);
            }
        }

#pragma unroll 1
        for (int kk = 0; kk < KRANGE; ++kk) {
            const __half2* k2p = k2t2 + (size_t)(kk * 4 + tg) * 8;
            uint4 kr0 = *(const uint4*)(k2p);
            uint4 kr1 = *(const uint4*)(k2p + 4);
            const unsigned kh[8] = {kr0.x, kr0.y, kr0.z, kr0.w,
                                    kr1.x, kr1.y, kr1.z, kr1.w};

            unsigned aa[4][4];
#pragma unroll
            for (int kc = 0; kc < 4; ++kc) {
                __half2 p0 = u2h2(kh[kc * 2]);
                __half2 p1 = u2h2(kh[kc * 2 + 1]);
                aa[kc][0] = hmul2u(qa[kc][0], p0);
                aa[kc][1] = hmul2u(qa[kc][1], p0);
                aa[kc][2] = hmul2u(qa[kc][2], p1);
                aa[kc][3] = hmul2u(qa[kc][3], p1);
            }

            float sc[4][4];
#pragma unroll
            for (int nt = 0; nt < 4; ++nt)
#pragma unroll
                for (int r = 0; r < 4; ++r) sc[nt][r] = -M_LOG2;
#pragma unroll
            for (int kc = 0; kc < 4; ++kc)
#pragma unroll
                for (int nt = 0; nt < 4; ++nt)
                    mma16816(sc[nt], aa[kc][0], aa[kc][1], aa[kc][2], aa[kc][3],
                             bsf[kc][nt][0], bsf[kc][nt][1]);

            unsigned pa[2][4];
#pragma unroll
            for (int kc = 0; kc < 2; ++kc) {
                pa[kc][0] = p2exp(sc[2 * kc][0],     sc[2 * kc][1]);
                pa[kc][1] = p2exp(sc[2 * kc][2],     sc[2 * kc][3]);
                pa[kc][2] = p2exp(sc[2 * kc + 1][0], sc[2 * kc + 1][1]);
                pa[kc][3] = p2exp(sc[2 * kc + 1][2], sc[2 * kc + 1][3]);
            }

            mma16816(cl, pa[0][0], pa[0][1], pa[0][2], pa[0][3], BONES, BONES);
            mma16816(cl, pa[1][0], pa[1][1], pa[1][2], pa[1][3], BONES, BONES);

            const __half* v2p = v2t + (size_t)(kk * 8 + g) * 8;
            uint4 vraw = *(const uint4*)(v2p);
            const unsigned vhp[4] = {vraw.x, vraw.y, vraw.z, vraw.w};

#pragma unroll
            for (int nt = 0; nt < 8; ++nt) {
                __half2 pair = u2h2(vhp[nt >> 1]);
                __half2 vdd  = (nt & 1) ? __high2half2(pair) : __low2half2(pair);
#pragma unroll
                for (int kc = 0; kc < 2; ++kc) {
                    unsigned b0 = hmul2u(bvf[kc][nt][0], vdd);
                    unsigned b1 = hmul2u(bvf[kc][nt][1], vdd);
                    mma16816(pv[nt], pa[kc][0], pa[kc][1], pa[kc][2], pa[kc][3],
                             b0, b1);
                }
            }
        }
    }

    const int row0 = bh * SEQ + i0 + warp * 16 + g;
    const int row1 = row0 + 8;
    const int p0   = split * BHD * SEQ + row0;
    const int p1   = split * BHD * SEQ + row1;
    if (tg == 0) {
        pl[p0] = cl[0];
        pl[p1] = cl[2];
    }
#pragma unroll
    for (int nt = 0; nt < 8; ++nt) {
        int d = nt * 8 + 2 * tg;
        *(float2*)(pacc + (size_t)p0 * DH + d) = make_float2(pv[nt][0], pv[nt][1]);
        *(float2*)(pacc + (size_t)p1 * DH + d) = make_float2(pv[nt][2], pv[nt][3]);
    }
}

// ---------------------------------------------------------------------------
// Combine KSPLIT partials; write attn as fp16 hi/lo at [b,n,h*64+d].
// ---------------------------------------------------------------------------
__global__ __launch_bounds__(256) void combine_kernel(
    const float* __restrict__ pacc, const float* __restrict__ pl,
    __half* __restrict__ ahi, __half* __restrict__ alo)
{
    const int row = blockIdx.x * 4 + (threadIdx.x >> 6);
    const int d   = threadIdx.x & 63;

    float den = 0.f, num = 0.f;
#pragma unroll
    for (int s = 0; s < KSPLIT; ++s) {
        int idx = s * BHD * SEQ + row;
        den += pl[idx];
        num += pacc[(size_t)idx * DH + d];
    }
    float a = num / den;

    const int bh = row / SEQ, n = row % SEQ;
    const int b = bh >> 3, h = bh & 7;
    const int o = (b * SEQ + n) * DIMM + h * DH + d;
    __half hi = __float2half_rn(a);
    ahi[o] = hi;
    alo[o] = __float2half_rn(a - __half2float(hi));
}

// ---------------------------------------------------------------------------
extern "C" void kernel_launch(void* const* d_in, const int* in_sizes, int n_in,
                              void* d_out, int out_size)
{
    (void)in_sizes; (void)n_in; (void)out_size;
    const float* tokens = (const float*)d_in[0];
    const float* w_qkv  = (const float*)d_in[1];
    const float* w_out  = (const float*)d_in[2];
    const float* qw     = (const float*)d_in[3];
    const float* k1w    = (const float*)d_in[4];
    const float* k2w    = (const float*)d_in[5];
    const float* v1w    = (const float*)d_in[6];
    const float* v2w    = (const float*)d_in[7];
    float* out = (float*)d_out;

    float *qkv, *pacc, *plv;
    __half *hq, *hk1, *hk2, *hv1, *hv2;
    __half *th, *tl, *wqh, *wql, *woh, *wol, *ah, *al;
    cudaGetSymbolAddress((void**)&qkv,  g_qkv);
    cudaGetSymbolAddress((void**)&hq,   g_hq);
    cudaGetSymbolAddress((void**)&hk1,  g_hk1);
    cudaGetSymbolAddress((void**)&hk2,  g_hk2);
    cudaGetSymbolAddress((void**)&hv1,  g_hv1);
    cudaGetSymbolAddress((void**)&hv2,  g_hv2);
    cudaGetSymbolAddress((void**)&pacc, g_pacc);
    cudaGetSymbolAddress((void**)&plv,  g_pl);
    cudaGetSymbolAddress((void**)&th,   g_th);
    cudaGetSymbolAddress((void**)&tl,   g_tl);
    cudaGetSymbolAddress((void**)&wqh,  g_wqh);
    cudaGetSymbolAddress((void**)&wql,  g_wql);
    cudaGetSymbolAddress((void**)&woh,  g_woh);
    cudaGetSymbolAddress((void**)&wol,  g_wol);
    cudaGetSymbolAddress((void**)&ah,   g_ah);
    cudaGetSymbolAddress((void**)&al,   g_al);

    cudaFuncSetAttribute(attn_mma,
                         cudaFuncAttributeMaxDynamicSharedMemorySize,
                         ATTN_SMEM_BYTES);

    // 0) fused hi/lo splits of GEMM operands
    split3_fp16<<<(N0Q + N1Q + N2Q + 255) / 256, 256>>>(
        tokens, th, tl, w_qkv, wqh, wql, w_out, woh, wol);
    // 1) qkv = tokens @ w_qkv^T : [384,2560]
    gemm_nt_tch<<<dim3(QKV_C / 64, ROWS / 64), 256>>>(th, tl, wqh, wql, qkv,
                                                      ROWS, QKV_C, DIMM);
    // 2) rmsnorm + split -> fp16
    rmsnorm_kernel<<<ROWS * HEADS / 8, 256>>>(qkv, qw, k1w, k2w, v1w, v2w,
                                              hq, hk1, hk2, hv1, hv2);
    // 3) tensor-core 2-simplicial attention, static-max split-K (12 splits)
    attn_mma<<<dim3(KSPLIT, SEQ / ITILE, BHD), NTHR, ATTN_SMEM_BYTES>>>(
        hq, hk1, hk2, hv1, hv2, pacc, plv);
    // 4) combine partials -> attn hi/lo
    combine_kernel<<<BHD * SEQ / 4, 256>>>(pacc, plv, ah, al);
    // 5) out = attn @ w_out^T : [384,512]
    gemm_nt_tch<<<dim3(DIMM / 64, ROWS / 64), 256>>>(ah, al, woh, wol, out,
                                                     ROWS, DIMM, DIMM);
}

// round 10
// speedup vs baseline: 1.0373x; 1.0373x over previous
#include <cuda_runtime.h>
#include <cuda_fp16.h>
#include <math_constants.h>
#include <cstdint>

// ---------------------------------------------------------------------------
// HigherOrderAttention — R10: KSPLIT back to 6 (R9 regressed); attn kk-loop
//   unrolled x2 with software pipelining (S0,S1 -> exp0,exp1 -> PV0,PV1)
//   to double per-warp ILP (we are grid-limited, registers are free).
// ---------------------------------------------------------------------------

#define TOK_B   2
#define SEQ     192
#define DIMM    512
#define HEADS   8
#define DH      64
#define BHD     (TOK_B * HEADS)        // 16
#define QKV_C   2560
#define ROWS    (TOK_B * SEQ)          // 384
#define KSPLIT  6
#define KRANGE  (SEQ / KSPLIT)         // 32
#define ITILE   64
#define NWARP   4
#define NTHR    (NWARP * 32)           // 128
#define NJC     (SEQ / 32)             // 6

#define M_LOG2  7.2134752f             // 5 * log2(e)
#define QSCALE  0.18033688f            // 0.125 * log2(e)

// Scratch (device globals)
__device__ float  g_qkv [ROWS * QKV_C];
__device__ __half g_hq  [BHD * SEQ * DH];
__device__ __half g_hk1 [BHD * SEQ * DH];
__device__ __half g_hk2 [BHD * SEQ * DH];
__device__ __half g_hv1 [BHD * SEQ * DH];
__device__ __half g_hv2 [BHD * SEQ * DH];
__device__ float  g_pacc[KSPLIT * BHD * SEQ * DH];
__device__ float  g_pl  [KSPLIT * BHD * SEQ];
__device__ __half g_th  [ROWS * DIMM],  g_tl  [ROWS * DIMM];
__device__ __half g_wqh [QKV_C * DIMM], g_wql [QKV_C * DIMM];
__device__ __half g_woh [DIMM * DIMM],  g_wol [DIMM * DIMM];
__device__ __half g_ah  [ROWS * DIMM],  g_al  [ROWS * DIMM];

// ---------------------------------------------------------------------------
__device__ __forceinline__ void mma16816(float c[4],
                                         unsigned a0, unsigned a1,
                                         unsigned a2, unsigned a3,
                                         unsigned b0, unsigned b1)
{
    asm volatile(
        "mma.sync.aligned.m16n8k16.row.col.f32.f16.f16.f32 "
        "{%0,%1,%2,%3},{%4,%5,%6,%7},{%8,%9},{%0,%1,%2,%3};\n"
        : "+f"(c[0]), "+f"(c[1]), "+f"(c[2]), "+f"(c[3])
        : "r"(a0), "r"(a1), "r"(a2), "r"(a3), "r"(b0), "r"(b1));
}

__device__ __forceinline__ void ldsm_x4(unsigned r[4], const __half* p)
{
    unsigned sa = (unsigned)__cvta_generic_to_shared(p);
    asm volatile("ldmatrix.sync.aligned.m8n8.x4.shared.b16 {%0,%1,%2,%3}, [%4];"
                 : "=r"(r[0]), "=r"(r[1]), "=r"(r[2]), "=r"(r[3]) : "r"(sa));
}

__device__ __forceinline__ unsigned hmul2u(unsigned a, __half2 b)
{
    __half2 av = *reinterpret_cast<__half2*>(&a);
    __half2 r  = __hmul2(av, b);
    return *reinterpret_cast<unsigned*>(&r);
}

__device__ __forceinline__ __half2 u2h2(unsigned a)
{
    return *reinterpret_cast<__half2*>(&a);
}

__device__ __forceinline__ unsigned p2exp(float a, float b)
{
    __half2 h = __floats2half2_rn(a, b);
    unsigned x = *reinterpret_cast<unsigned*>(&h);
    unsigned r;
    asm("ex2.approx.f16x2 %0, %1;" : "=r"(r) : "r"(x));
    return r;
}

// ---------------------------------------------------------------------------
// Fused fp32 -> (hi,lo) fp16 split for 3 arrays.
// ---------------------------------------------------------------------------
__device__ __forceinline__ void split_quad(const float* __restrict__ x,
                                           __half* __restrict__ hi,
                                           __half* __restrict__ lo, int i)
{
    float4 v = ((const float4*)x)[i];
    __half hx = __float2half_rn(v.x), hy = __float2half_rn(v.y);
    __half hz = __float2half_rn(v.z), hw = __float2half_rn(v.w);
    ((__half2*)hi)[2 * i]     = __halves2half2(hx, hy);
    ((__half2*)hi)[2 * i + 1] = __halves2half2(hz, hw);
    ((__half2*)lo)[2 * i]     = __halves2half2(
        __float2half_rn(v.x - __half2float(hx)),
        __float2half_rn(v.y - __half2float(hy)));
    ((__half2*)lo)[2 * i + 1] = __halves2half2(
        __float2half_rn(v.z - __half2float(hz)),
        __float2half_rn(v.w - __half2float(hw)));
}

#define N0Q (ROWS * DIMM / 4)
#define N1Q (QKV_C * DIMM / 4)
#define N2Q (DIMM * DIMM / 4)

__global__ __launch_bounds__(256) void split3_fp16(
    const float* __restrict__ x0, __half* __restrict__ h0, __half* __restrict__ l0,
    const float* __restrict__ x1, __half* __restrict__ h1, __half* __restrict__ l1,
    const float* __restrict__ x2, __half* __restrict__ h2, __half* __restrict__ l2)
{
    int i = blockIdx.x * 256 + threadIdx.x;
    if (i < N0Q) {
        split_quad(x0, h0, l0, i);
    } else if (i < N0Q + N1Q) {
        split_quad(x1, h1, l1, i - N0Q);
    } else if (i < N0Q + N1Q + N2Q) {
        split_quad(x2, h2, l2, i - N0Q - N1Q);
    }
}

// ---------------------------------------------------------------------------
// Tensor-core NT GEMM on pre-split hi/lo fp16, ldmatrix + double buffer.
// ---------------------------------------------------------------------------
#define GS 40   // smem row stride in halves

__global__ __launch_bounds__(256) void gemm_nt_tch(
    const __half* __restrict__ Ah_, const __half* __restrict__ Al_,
    const __half* __restrict__ Bh_, const __half* __restrict__ Bl_,
    float* __restrict__ C, int M, int N, int K)
{
    __shared__ __half sm[2][4][64 * GS];

    const int t    = threadIdx.x;
    const int m0   = blockIdx.y * 64;
    const int n0   = blockIdx.x * 64;
    const int warp = t >> 5;
    const int lane = t & 31;
    const int g    = lane >> 2;
    const int tg   = lane & 3;
    const int wm   = warp >> 1;
    const int wn   = warp & 1;

    const int lrow = t >> 2;
    const int lc8  = (t & 3) * 8;

    const int a_off = (wm * 16 + (lane & 15)) * GS + 8 * (lane >> 4);
    const int b_row = wn * 32 + (lane & 7) + ((lane >> 4) & 1) * 8;
    const int b_c8  = ((lane >> 3) & 1) * 8;

    float c[4][4];
#pragma unroll
    for (int a = 0; a < 4; ++a)
#pragma unroll
        for (int b = 0; b < 4; ++b) c[a][b] = 0.f;

    const int NIT = K >> 5;
    uint4 ra, rb, rc, rd;

    {
        size_t ga = (size_t)(m0 + lrow) * K + lc8;
        size_t gb = (size_t)(n0 + lrow) * K + lc8;
        ra = *(const uint4*)(Ah_ + ga);
        rb = *(const uint4*)(Al_ + ga);
        rc = *(const uint4*)(Bh_ + gb);
        rd = *(const uint4*)(Bl_ + gb);
        __half* p = &sm[0][0][lrow * GS + lc8];
        *(uint4*)(p)               = ra;
        *(uint4*)(p + 64 * GS)     = rb;
        *(uint4*)(p + 2 * 64 * GS) = rc;
        *(uint4*)(p + 3 * 64 * GS) = rd;
    }
    __syncthreads();

#pragma unroll 1
    for (int it = 0; it < NIT; ++it) {
        const int cur = it & 1;

        if (it + 1 < NIT) {
            size_t ga = (size_t)(m0 + lrow) * K + (it + 1) * 32 + lc8;
            size_t gb = (size_t)(n0 + lrow) * K + (it + 1) * 32 + lc8;
            ra = *(const uint4*)(Ah_ + ga);
            rb = *(const uint4*)(Al_ + ga);
            rc = *(const uint4*)(Bh_ + gb);
            rd = *(const uint4*)(Bl_ + gb);
        }

        const __half* Ahs = sm[cur][0];
        const __half* Als = sm[cur][1];
        const __half* Bhs = sm[cur][2];
        const __half* Bls = sm[cur][3];

#pragma unroll
        for (int kc = 0; kc < 2; ++kc) {
            const int ko = kc * 16;
            unsigned ah[4], al[4];
            ldsm_x4(ah, Ahs + a_off + ko);
            ldsm_x4(al, Als + a_off + ko);
#pragma unroll
            for (int p = 0; p < 2; ++p) {
                unsigned bh[4], bl[4];
                const int bo = (b_row + p * 16) * GS + ko + b_c8;
                ldsm_x4(bh, Bhs + bo);
                ldsm_x4(bl, Bls + bo);
                mma16816(c[2 * p],     ah[0], ah[1], ah[2], ah[3], bh[0], bh[1]);
                mma16816(c[2 * p],     ah[0], ah[1], ah[2], ah[3], bl[0], bl[1]);
                mma16816(c[2 * p],     al[0], al[1], al[2], al[3], bh[0], bh[1]);
                mma16816(c[2 * p + 1], ah[0], ah[1], ah[2], ah[3], bh[2], bh[3]);
                mma16816(c[2 * p + 1], ah[0], ah[1], ah[2], ah[3], bl[2], bl[3]);
                mma16816(c[2 * p + 1], al[0], al[1], al[2], al[3], bh[2], bh[3]);
            }
        }

        if (it + 1 < NIT) {
            __half* p = &sm[cur ^ 1][0][lrow * GS + lc8];
            *(uint4*)(p)               = ra;
            *(uint4*)(p + 64 * GS)     = rb;
            *(uint4*)(p + 2 * 64 * GS) = rc;
            *(uint4*)(p + 3 * 64 * GS) = rd;
            __syncthreads();
        }
    }

    const int row0 = m0 + wm * 16 + g;
    const int row1 = row0 + 8;
#pragma unroll
    for (int nt = 0; nt < 4; ++nt) {
        const int col = n0 + wn * 32 + nt * 8 + 2 * tg;
        *(float2*)(C + (size_t)row0 * N + col) = make_float2(c[nt][0], c[nt][1]);
        *(float2*)(C + (size_t)row1 * N + col) = make_float2(c[nt][2], c[nt][3]);
    }
}

// ---------------------------------------------------------------------------
// RMSNorm + head split; emits fp16 (q pre-scaled by 0.125*log2e).
// ---------------------------------------------------------------------------
__device__ __forceinline__ void rms_one_h(const float* __restrict__ x,
                                          const float* __restrict__ w,
                                          __half* __restrict__ y, int lane,
                                          float scale)
{
    float x0 = x[lane];
    float x1 = x[lane + 32];
    float ss = x0 * x0 + x1 * x1;
#pragma unroll
    for (int o = 16; o >= 1; o >>= 1)
        ss += __shfl_xor_sync(0xffffffffu, ss, o);
    float inv = rsqrtf(ss * (1.0f / 64.0f) + 1.1920929e-07f) * scale;
    y[lane]      = __float2half(x0 * inv * w[lane]);
    y[lane + 32] = __float2half(x1 * inv * w[lane + 32]);
}

__global__ __launch_bounds__(256) void rmsnorm_kernel(
    const float* __restrict__ qkv,
    const float* __restrict__ qw,  const float* __restrict__ k1w,
    const float* __restrict__ k2w, const float* __restrict__ v1w,
    const float* __restrict__ v2w,
    __half* __restrict__ hq,  __half* __restrict__ hk1, __half* __restrict__ hk2,
    __half* __restrict__ hv1, __half* __restrict__ hv2)
{
    const int wid  = threadIdx.x >> 5;
    const int lane = threadIdx.x & 31;
    const int id   = blockIdx.x * 8 + wid;
    const int h    = id & 7;
    const int bn   = id >> 3;
    const int b    = bn / SEQ;
    const int n    = bn % SEQ;

    const float* base = qkv + bn * QKV_C;
    const int dst = ((b * HEADS + h) * SEQ + n) * DH;

    rms_one_h(base + h * DH,              qw,  hq  + dst, lane, QSCALE);
    rms_one_h(base + 512  + h * 128,      k1w, hk1 + dst, lane, 1.0f);
    rms_one_h(base + 512  + h * 128 + DH, k2w, hk2 + dst, lane, 1.0f);
    rms_one_h(base + 1536 + h * 128,      v1w, hv1 + dst, lane, 1.0f);
    rms_one_h(base + 1536 + h * 128 + DH, v2w, hv2 + dst, lane, 1.0f);
}

// ---------------------------------------------------------------------------
// Tensor-core attention, static-max softmax, kk-loop unrolled x2.
// ---------------------------------------------------------------------------
#define K1_STRIDE 72
#define SM_K1   (SEQ * K1_STRIDE)
#define SM_V1T  (DH * 200)
#define SM_Q    (ITILE * DH)
#define SM_K2   (KRANGE * DH)
#define SM_V2   (KRANGE * DH)
#define ATTN_SMEM_HALVES (SM_K1 + SM_V1T + SM_Q + SM_K2 + SM_V2)
#define ATTN_SMEM_BYTES  (ATTN_SMEM_HALVES * 2)

__global__ __launch_bounds__(NTHR, 2) void attn_mma(
    const __half* __restrict__ hq,  const __half* __restrict__ hk1,
    const __half* __restrict__ hk2, const __half* __restrict__ hv1,
    const __half* __restrict__ hv2,
    float* __restrict__ pacc, float* __restrict__ pl)
{
    extern __shared__ __align__(16) __half smh[];
    __half*  k1s  = smh;
    __half*  v1t  = k1s + SM_K1;
    __half*  qs   = v1t + SM_V1T;
    __half2* k2t2 = (__half2*)(qs + SM_Q);
    __half*  v2t  = qs + SM_Q + SM_K2;

    const int split = blockIdx.x;
    const int i0    = blockIdx.y * ITILE;
    const int bh    = blockIdx.z;
    const int t     = threadIdx.x;
    const int kbeg  = split * KRANGE;

    const __half* k1b = hk1 + bh * SEQ * DH;
    const __half* v1b = hv1 + bh * SEQ * DH;
    const __half* k2b = hk2 + (bh * SEQ + kbeg) * DH;
    const __half* v2b = hv2 + (bh * SEQ + kbeg) * DH;
    const __half* qb  = hq  + (bh * SEQ + i0) * DH;

    for (int e = t; e < SEQ * DH; e += NTHR) {
        int j = e >> 6, d = e & 63;
        k1s[j * K1_STRIDE + d] = k1b[e];
        v1t[d * 200 + j]       = v1b[e];
    }
    for (int e = t; e < ITILE * DH; e += NTHR) qs[e] = qb[e];
    for (int e = t; e < KRANGE * 32; e += NTHR) {
        int kk = e >> 5, r = e & 31;
        int tg_ = r >> 3, s = r & 7;
        int col = (s >> 1) * 16 + (s & 1) * 8 + tg_ * 2;
        k2t2[e] = *(const __half2*)(k2b + kk * DH + col);
    }
    for (int e = t; e < KRANGE * 64; e += NTHR) {
        int kk = e >> 6, r = e & 63;
        int g_ = r >> 3, nt = r & 7;
        v2t[e] = v2b[kk * DH + nt * 8 + g_];
    }
    __syncthreads();

    const int warp = t >> 5;
    const int lane = t & 31;
    const int g    = lane >> 2;
    const int tg   = lane & 3;

    const unsigned BONES = 0x3C003C00u;

    unsigned qa[4][4];
    {
        const __half* qr0 = qs + (warp * 16 + g) * DH;
        const __half* qr8 = qs + (warp * 16 + g + 8) * DH;
#pragma unroll
        for (int kc = 0; kc < 4; ++kc) {
            qa[kc][0] = *(const unsigned*)(qr0 + kc * 16 + 2 * tg);
            qa[kc][1] = *(const unsigned*)(qr8 + kc * 16 + 2 * tg);
            qa[kc][2] = *(const unsigned*)(qr0 + kc * 16 + 2 * tg + 8);
            qa[kc][3] = *(const unsigned*)(qr8 + kc * 16 + 2 * tg + 8);
        }
    }

    float pv[8][4];
#pragma unroll
    for (int n = 0; n < 8; ++n)
#pragma unroll
        for (int r = 0; r < 4; ++r) pv[n][r] = 0.f;
    float cl[4] = {0.f, 0.f, 0.f, 0.f};

#pragma unroll 1
    for (int jc = 0; jc < NJC; ++jc) {
        unsigned bsf[4][4][2];
        unsigned bvf[2][8][2];
#pragma unroll
        for (int nt = 0; nt < 4; ++nt) {
            const __half* kr = k1s + (jc * 32 + nt * 8 + g) * K1_STRIDE + 2 * tg;
#pragma unroll
            for (int kc = 0; kc < 4; ++kc) {
                bsf[kc][nt][0] = *(const unsigned*)(kr + kc * 16);
                bsf[kc][nt][1] = *(const unsigned*)(kr + kc * 16 + 8);
            }
        }
#pragma unroll
        for (int nt = 0; nt < 8; ++nt) {
            const __half* vr = v1t + (nt * 8 + g) * 200 + jc * 32 + 2 * tg;
#pragma unroll
            for (int kc = 0; kc < 2; ++kc) {
                bvf[kc][nt][0] = *(const unsigned*)(vr + kc * 16);
                bvf[kc][nt][1] = *(const unsigned*)(vr + kc * 16 + 8);
            }
        }

#pragma unroll 1
        for (int kk = 0; kk < KRANGE; kk += 2) {
            // ======== S phase for steps kk (u=0) and kk+1 (u=1) ===========
            float sc[2][4][4];
#pragma unroll
            for (int u = 0; u < 2; ++u) {
                const __half2* k2p = k2t2 + (size_t)((kk + u) * 4 + tg) * 8;
                uint4 kr0 = *(const uint4*)(k2p);
                uint4 kr1 = *(const uint4*)(k2p + 4);
                const unsigned kh[8] = {kr0.x, kr0.y, kr0.z, kr0.w,
                                        kr1.x, kr1.y, kr1.z, kr1.w};
                unsigned aa[4][4];
#pragma unroll
                for (int kc = 0; kc < 4; ++kc) {
                    __half2 p0 = u2h2(kh[kc * 2]);
                    __half2 p1 = u2h2(kh[kc * 2 + 1]);
                    aa[kc][0] = hmul2u(qa[kc][0], p0);
                    aa[kc][1] = hmul2u(qa[kc][1], p0);
                    aa[kc][2] = hmul2u(qa[kc][2], p1);
                    aa[kc][3] = hmul2u(qa[kc][3], p1);
                }
#pragma unroll
                for (int nt = 0; nt < 4; ++nt)
#pragma unroll
                    for (int r = 0; r < 4; ++r) sc[u][nt][r] = -M_LOG2;
#pragma unroll
                for (int kc = 0; kc < 4; ++kc)
#pragma unroll
                    for (int nt = 0; nt < 4; ++nt)
                        mma16816(sc[u][nt], aa[kc][0], aa[kc][1],
                                 aa[kc][2], aa[kc][3],
                                 bsf[kc][nt][0], bsf[kc][nt][1]);
            }

            // ======== exp phase (both sub-steps) ==========================
            unsigned pa[2][2][4];
#pragma unroll
            for (int u = 0; u < 2; ++u)
#pragma unroll
                for (int kc = 0; kc < 2; ++kc) {
                    pa[u][kc][0] = p2exp(sc[u][2 * kc][0],     sc[u][2 * kc][1]);
                    pa[u][kc][1] = p2exp(sc[u][2 * kc][2],     sc[u][2 * kc][3]);
                    pa[u][kc][2] = p2exp(sc[u][2 * kc + 1][0], sc[u][2 * kc + 1][1]);
                    pa[u][kc][3] = p2exp(sc[u][2 * kc + 1][2], sc[u][2 * kc + 1][3]);
                }

            // ======== l accumulation ======================================
#pragma unroll
            for (int u = 0; u < 2; ++u) {
                mma16816(cl, pa[u][0][0], pa[u][0][1], pa[u][0][2], pa[u][0][3],
                         BONES, BONES);
                mma16816(cl, pa[u][1][0], pa[u][1][1], pa[u][1][2], pa[u][1][3],
                         BONES, BONES);
            }

            // ======== PV phase (both sub-steps) ===========================
#pragma unroll
            for (int u = 0; u < 2; ++u) {
                const __half* v2p = v2t + (size_t)((kk + u) * 8 + g) * 8;
                uint4 vraw = *(const uint4*)(v2p);
                const unsigned vhp[4] = {vraw.x, vraw.y, vraw.z, vraw.w};
#pragma unroll
                for (int nt = 0; nt < 8; ++nt) {
                    __half2 pair = u2h2(vhp[nt >> 1]);
                    __half2 vdd  = (nt & 1) ? __high2half2(pair)
                                            : __low2half2(pair);
#pragma unroll
                    for (int kc = 0; kc < 2; ++kc) {
                        unsigned b0 = hmul2u(bvf[kc][nt][0], vdd);
                        unsigned b1 = hmul2u(bvf[kc][nt][1], vdd);
                        mma16816(pv[nt], pa[u][kc][0], pa[u][kc][1],
                                 pa[u][kc][2], pa[u][kc][3], b0, b1);
                    }
                }
            }
        }
    }

    const int row0 = bh * SEQ + i0 + warp * 16 + g;
    const int row1 = row0 + 8;
    const int p0   = split * BHD * SEQ + row0;
    const int p1   = split * BHD * SEQ + row1;
    if (tg == 0) {
        pl[p0] = cl[0];
        pl[p1] = cl[2];
    }
#pragma unroll
    for (int nt = 0; nt < 8; ++nt) {
        int d = nt * 8 + 2 * tg;
        *(float2*)(pacc + (size_t)p0 * DH + d) = make_float2(pv[nt][0], pv[nt][1]);
        *(float2*)(pacc + (size_t)p1 * DH + d) = make_float2(pv[nt][2], pv[nt][3]);
    }
}

// ---------------------------------------------------------------------------
// Combine KSPLIT partials; write attn as fp16 hi/lo at [b,n,h*64+d].
// ---------------------------------------------------------------------------
__global__ __launch_bounds__(256) void combine_kernel(
    const float* __restrict__ pacc, const float* __restrict__ pl,
    __half* __restrict__ ahi, __half* __restrict__ alo)
{
    const int row = blockIdx.x * 4 + (threadIdx.x >> 6);
    const int d   = threadIdx.x & 63;

    float den = 0.f, num = 0.f;
#pragma unroll
    for (int s = 0; s < KSPLIT; ++s) {
        int idx = s * BHD * SEQ + row;
        den += pl[idx];
        num += pacc[(size_t)idx * DH + d];
    }
    float a = num / den;

    const int bh = row / SEQ, n = row % SEQ;
    const int b = bh >> 3, h = bh & 7;
    const int o = (b * SEQ + n) * DIMM + h * DH + d;
    __half hi = __float2half_rn(a);
    ahi[o] = hi;
    alo[o] = __float2half_rn(a - __half2float(hi));
}

// ---------------------------------------------------------------------------
extern "C" void kernel_launch(void* const* d_in, const int* in_sizes, int n_in,
                              void* d_out, int out_size)
{
    (void)in_sizes; (void)n_in; (void)out_size;
    const float* tokens = (const float*)d_in[0];
    const float* w_qkv  = (const float*)d_in[1];
    const float* w_out  = (const float*)d_in[2];
    const float* qw     = (const float*)d_in[3];
    const float* k1w    = (const float*)d_in[4];
    const float* k2w    = (const float*)d_in[5];
    const float* v1w    = (const float*)d_in[6];
    const float* v2w    = (const float*)d_in[7];
    float* out = (float*)d_out;

    float *qkv, *pacc, *plv;
    __half *hq, *hk1, *hk2, *hv1, *hv2;
    __half *th, *tl, *wqh, *wql, *woh, *wol, *ah, *al;
    cudaGetSymbolAddress((void**)&qkv,  g_qkv);
    cudaGetSymbolAddress((void**)&hq,   g_hq);
    cudaGetSymbolAddress((void**)&hk1,  g_hk1);
    cudaGetSymbolAddress((void**)&hk2,  g_hk2);
    cudaGetSymbolAddress((void**)&hv1,  g_hv1);
    cudaGetSymbolAddress((void**)&hv2,  g_hv2);
    cudaGetSymbolAddress((void**)&pacc, g_pacc);
    cudaGetSymbolAddress((void**)&plv,  g_pl);
    cudaGetSymbolAddress((void**)&th,   g_th);
    cudaGetSymbolAddress((void**)&tl,   g_tl);
    cudaGetSymbolAddress((void**)&wqh,  g_wqh);
    cudaGetSymbolAddress((void**)&wql,  g_wql);
    cudaGetSymbolAddress((void**)&woh,  g_woh);
    cudaGetSymbolAddress((void**)&wol,  g_wol);
    cudaGetSymbolAddress((void**)&ah,   g_ah);
    cudaGetSymbolAddress((void**)&al,   g_al);

    cudaFuncSetAttribute(attn_mma,
                         cudaFuncAttributeMaxDynamicSharedMemorySize,
                         ATTN_SMEM_BYTES);

    // 0) fused hi/lo splits of GEMM operands
    split3_fp16<<<(N0Q + N1Q + N2Q + 255) / 256, 256>>>(
        tokens, th, tl, w_qkv, wqh, wql, w_out, woh, wol);
    // 1) qkv = tokens @ w_qkv^T : [384,2560]
    gemm_nt_tch<<<dim3(QKV_C / 64, ROWS / 64), 256>>>(th, tl, wqh, wql, qkv,
                                                      ROWS, QKV_C, DIMM);
    // 2) rmsnorm + split -> fp16
    rmsnorm_kernel<<<ROWS * HEADS / 8, 256>>>(qkv, qw, k1w, k2w, v1w, v2w,
                                              hq, hk1, hk2, hv1, hv2);
    // 3) tensor-core 2-simplicial attention, static-max split-K (6 splits)
    attn_mma<<<dim3(KSPLIT, SEQ / ITILE, BHD), NTHR, ATTN_SMEM_BYTES>>>(
        hq, hk1, hk2, hv1, hv2, pacc, plv);
    // 4) combine partials -> attn hi/lo
    combine_kernel<<<BHD * SEQ / 4, 256>>>(pacc, plv, ah, al);
    // 5) out = attn @ w_out^T : [384,512]
    gemm_nt_tch<<<dim3(DIMM / 64, ROWS / 64), 256>>>(ah, al, woh, wol, out,
                                                     ROWS, DIMM, DIMM);
}